// round 9
// baseline (speedup 1.0000x reference)
#include <cuda_runtime.h>
#include <cuda_bf16.h>
#include <cstdint>

// Problem constants
#define NN    4096
#define INF_  256
#define FF    64
#define HH    4
#define CC    256      // HH*FF
#define NEG_SLOPE 0.2f

// Attention tiling
#define JS      4
#define JRANGE  (NN / JS)         // 1024
#define JT      64
#define NTILES  (JRANGE / JT)     // 16
#define ITM     128

#define HS_PITCH  264             // floats; conflict-free fragment reads
#define ADJ_PITCH 68
#define HS_BUF    (JT * HS_PITCH)        // 16896 floats per buffer
#define ADJ_BUF   (ITM * ADJ_PITCH)      // 8704
#define ER_BUF    (JT * HH * 2)          // 512 floats
#define OFF_HS    0
#define OFF_ADJ   (2 * HS_BUF)                    // 33792
#define OFF_ER    (OFF_ADJ + 2 * ADJ_BUF)         // 51200
#define ATTN_SMEM ((OFF_ER + 2 * ER_BUF) * 4)     // 208896 B

// Scratch (device globals: allocation-free rule)
__device__ float  g_h[NN * CC];            // 4 MB fp32 (for el/er)
__device__ float  g_hr[NN * CC];           // 4 MB tf32-rounded (mma B operand)
__device__ float2 g_eL[NN * HH];           // (exp(el), exp(0.2*el))
__device__ float2 g_eR[NN * HH];
__device__ float  g_acc[JS * NN * CC];     // 16 MB partial numerators
__device__ float  g_z[JS * NN * HH];

// ---- packed f32x2 helpers (gemm1) ----
__device__ __forceinline__ unsigned long long pk2(float lo, float hi) {
    unsigned long long r;
    asm("mov.b64 %0, {%1, %2};" : "=l"(r) : "f"(lo), "f"(hi));
    return r;
}
__device__ __forceinline__ void upk2(unsigned long long v, float& lo, float& hi) {
    asm("mov.b64 {%0, %1}, %2;" : "=f"(lo), "=f"(hi) : "l"(v));
}
#define FFMA2(d, a, b) \
    asm("fma.rn.f32x2 %0, %1, %2, %0;" : "+l"(d) : "l"(a), "l"(b))

__device__ __forceinline__ uint32_t tf32r(float f) {   // round-to-nearest tf32
    uint32_t r;
    asm("cvt.rna.tf32.f32 %0, %1;" : "=r"(r) : "f"(f));
    return r;
}

// ---- tf32 mma ----
__device__ __forceinline__ void mma_tf32(float* d, uint32_t a0, uint32_t a1,
                                         uint32_t a2, uint32_t a3,
                                         uint32_t b0, uint32_t b1) {
    asm volatile(
        "mma.sync.aligned.m16n8k8.row.col.f32.tf32.tf32.f32 "
        "{%0,%1,%2,%3}, {%4,%5,%6,%7}, {%8,%9}, {%0,%1,%2,%3};"
        : "+f"(d[0]), "+f"(d[1]), "+f"(d[2]), "+f"(d[3])
        : "r"(a0), "r"(a1), "r"(a2), "r"(a3), "r"(b0), "r"(b1));
}

// ---- cp.async ----
__device__ __forceinline__ uint32_t smem_u32(const void* p) {
    uint32_t a;
    asm("{ .reg .u64 t; cvta.to.shared.u64 t, %1; cvt.u32.u64 %0, t; }"
        : "=r"(a) : "l"(p));
    return a;
}
#define CP16(dst, src) \
    asm volatile("cp.async.cg.shared.global [%0], [%1], 16;" \
                 :: "r"(dst), "l"(src) : "memory")
#define CP_COMMIT() asm volatile("cp.async.commit_group;" ::: "memory")
#define CP_WAIT0()  asm volatile("cp.async.wait_group 0;" ::: "memory")

// ---------------------------------------------------------------------------
// Kernel 1: h = x @ W (fp32). Writes g_h (fp32) and g_hr (tf32-rounded).
// ---------------------------------------------------------------------------
__global__ void k_gemm_xw(const float* __restrict__ x,
                          const float* __restrict__ W) {
    __shared__ float x_s[64][17];
    __shared__ __align__(16) float W_s[16][64];

    const int t  = threadIdx.x;
    const int i0 = blockIdx.x * 64;
    const int n0 = blockIdx.y * 64;
    const int tcx = t & 15;
    const int trx = t >> 4;

    unsigned long long acc2[4][2];
#pragma unroll
    for (int m = 0; m < 4; m++) { acc2[m][0] = 0ull; acc2[m][1] = 0ull; }

    for (int k0 = 0; k0 < INF_; k0 += 16) {
#pragma unroll
        for (int k = 0; k < 4; k++) {
            int idx = k * 256 + t;
            x_s[idx >> 4][idx & 15] = x[(i0 + (idx >> 4)) * INF_ + k0 + (idx & 15)];
        }
#pragma unroll
        for (int k = 0; k < 4; k++) {
            int idx = k * 256 + t;
            W_s[idx >> 6][idx & 63] = W[(k0 + (idx >> 6)) * CC + n0 + (idx & 63)];
        }
        __syncthreads();
#pragma unroll
        for (int kk = 0; kk < 16; kk++) {
            ulonglong2 B = *(const ulonglong2*)&W_s[kk][tcx * 4];
#pragma unroll
            for (int m = 0; m < 4; m++) {
                float av = x_s[trx * 4 + m][kk];
                unsigned long long a2 = pk2(av, av);
                FFMA2(acc2[m][0], a2, B.x);
                FFMA2(acc2[m][1], a2, B.y);
            }
        }
        __syncthreads();
    }
#pragma unroll
    for (int m = 0; m < 4; m++) {
        float4 v;
        upk2(acc2[m][0], v.x, v.y);
        upk2(acc2[m][1], v.z, v.w);
        size_t o = (size_t)(i0 + trx * 4 + m) * CC + n0 + tcx * 4;
        *(float4*)&g_h[o] = v;
        float4 vr = make_float4(
            __uint_as_float(tf32r(v.x)), __uint_as_float(tf32r(v.y)),
            __uint_as_float(tf32r(v.z)), __uint_as_float(tf32r(v.w)));
        *(float4*)&g_hr[o] = vr;
    }
}

// ---------------------------------------------------------------------------
// Kernel 2: el/er dots (from fp32 h) -> factored exponentials
// ---------------------------------------------------------------------------
__global__ void k_elr(const float* __restrict__ a) {
    const int i    = blockIdx.x;
    const int wid  = threadIdx.x >> 5;
    const int lane = threadIdx.x & 31;

    float v1 = g_h[i * CC + wid * FF + lane];
    float v2 = g_h[i * CC + wid * FF + lane + 32];
    float el = v1 * a[lane]      + v2 * a[lane + 32];
    float er = v1 * a[64 + lane] + v2 * a[96 + lane];
#pragma unroll
    for (int off = 16; off > 0; off >>= 1) {
        el += __shfl_xor_sync(0xffffffffu, el, off);
        er += __shfl_xor_sync(0xffffffffu, er, off);
    }
    if (lane == 0) {
        g_eL[i * HH + wid] = make_float2(__expf(el), __expf(NEG_SLOPE * el));
        g_eR[i * HH + wid] = make_float2(__expf(er), __expf(NEG_SLOPE * er));
    }
}

// ---------------------------------------------------------------------------
// Kernel 3: fused attention via mma.sync tf32, cp.async double-buffered,
// JT=64 tiles (16 barriers total). A=w rounded via +0x1000; B pre-rounded.
// ---------------------------------------------------------------------------
__global__ void __launch_bounds__(512, 1) k_attn(const float* __restrict__ adj) {
    extern __shared__ __align__(16) float sm[];
    const uint32_t sm_b = smem_u32(sm);

    const int tid  = threadIdx.x;
    const int wid  = tid >> 5;
    const int lane = tid & 31;
    const int hh   = wid >> 2;
    const int wm   = wid & 3;
    const int m0   = wm * 32;
    const int gid  = lane >> 2;    // 0..7
    const int tig  = lane & 3;     // 0..3
    const int i0   = blockIdx.x * ITM;
    const int js   = blockIdx.y;
    const int jbase = js * JRANGE;
    const int cbase = hh * 64 + gid;

    // row exp-factors pinned in registers
    float2 P[4];
#pragma unroll
    for (int m = 0; m < 2; m++)
#pragma unroll
        for (int ri = 0; ri < 2; ri++)
            P[m * 2 + ri] = g_eL[(i0 + m0 + 16 * m + 8 * ri + gid) * HH + hh];

    float acc[2][8][4];
#pragma unroll
    for (int m = 0; m < 2; m++)
#pragma unroll
        for (int n = 0; n < 8; n++)
#pragma unroll
            for (int q = 0; q < 4; q++) acc[m][n][q] = 0.f;
    float z[4] = {0.f, 0.f, 0.f, 0.f};

    // ---- issue staging for tile t into buffer b ----
    auto issue = [&](int t, int b) {
        const int j0 = jbase + t * JT;
        const uint32_t hsb  = sm_b + (OFF_HS  + b * HS_BUF)  * 4;
        const uint32_t adjb = sm_b + (OFF_ADJ + b * ADJ_BUF) * 4;
        const uint32_t erb  = sm_b + (OFF_ER  + b * ER_BUF)  * 4;
        // hs: 64 rows x 256 floats = 4096 chunks
#pragma unroll
        for (int q = 0; q < 8; q++) {
            int idx = q * 512 + tid;
            int r = idx >> 6, c4 = (idx & 63) * 4;
            CP16(hsb + (r * HS_PITCH + c4) * 4,
                 (const char*)&g_hr[(size_t)(j0 + r) * CC + c4]);
        }
        // adj: 128 rows x 64 floats = 2048 chunks
#pragma unroll
        for (int q = 0; q < 4; q++) {
            int idx = q * 512 + tid;
            int r = idx >> 4, c4 = (idx & 15) * 4;
            CP16(adjb + (r * ADJ_PITCH + c4) * 4,
                 (const char*)&adj[(size_t)(i0 + r) * NN + j0 + c4]);
        }
        // er: 64 x 4 float2 = 128 chunks
        if (tid < 128)
            CP16(erb + tid * 16, (const char*)&g_eR[j0 * HH] + tid * 16);
        CP_COMMIT();
    };

    issue(0, 0);

    for (int t = 0; t < NTILES; t++) {
        const int b = t & 1;
        CP_WAIT0();
        __syncthreads();               // tile t visible; tile t-1 compute done
        if (t + 1 < NTILES) issue(t + 1, b ^ 1);

        const float*  hs   = sm + OFF_HS  + b * HS_BUF;
        const float*  adjs = sm + OFF_ADJ + b * ADJ_BUF;
        const float2* ers  = (const float2*)(sm + OFF_ER + b * ER_BUF);

#pragma unroll
        for (int k = 0; k < 8; k++) {
            const int jA = k * 8 + tig;
            const float2 Q0 = ers[jA * HH + hh];
            const float2 Q1 = ers[(jA + 4) * HH + hh];

            uint32_t b0[8], b1[8];
            const float* hr0 = hs + jA * HS_PITCH + cbase;
            const float* hr1 = hs + (jA + 4) * HS_PITCH + cbase;
#pragma unroll
            for (int n = 0; n < 8; n++) {
                b0[n] = __float_as_uint(hr0[n * 8]);
                b1[n] = __float_as_uint(hr1[n * 8]);
            }

#pragma unroll
            for (int m = 0; m < 2; m++) {
                const int ib = m0 + 16 * m + gid;
                float w00 = adjs[ib * ADJ_PITCH + jA] *
                            fmaxf(P[2 * m].x * Q0.x, P[2 * m].y * Q0.y);
                float w10 = adjs[(ib + 8) * ADJ_PITCH + jA] *
                            fmaxf(P[2 * m + 1].x * Q0.x, P[2 * m + 1].y * Q0.y);
                float w01 = adjs[ib * ADJ_PITCH + jA + 4] *
                            fmaxf(P[2 * m].x * Q1.x, P[2 * m].y * Q1.y);
                float w11 = adjs[(ib + 8) * ADJ_PITCH + jA + 4] *
                            fmaxf(P[2 * m + 1].x * Q1.x, P[2 * m + 1].y * Q1.y);
                z[2 * m]     += w00 + w01;
                z[2 * m + 1] += w10 + w11;
                // half-ulp rounding before HW tf32 truncation (w >= 0)
                uint32_t a0 = __float_as_uint(w00) + 0x1000u;
                uint32_t a1 = __float_as_uint(w10) + 0x1000u;
                uint32_t a2 = __float_as_uint(w01) + 0x1000u;
                uint32_t a3 = __float_as_uint(w11) + 0x1000u;
#pragma unroll
                for (int n = 0; n < 8; n++)
                    mma_tf32(acc[m][n], a0, a1, a2, a3, b0[n], b1[n]);
            }
        }
    }

    // ---- z reduce across quad lanes ----
#pragma unroll
    for (int q = 0; q < 4; q++) {
        z[q] += __shfl_xor_sync(0xffffffffu, z[q], 1);
        z[q] += __shfl_xor_sync(0xffffffffu, z[q], 2);
    }
    if (tig == 0) {
#pragma unroll
        for (int m = 0; m < 2; m++)
#pragma unroll
            for (int ri = 0; ri < 2; ri++) {
                int row = i0 + m0 + 16 * m + 8 * ri + gid;
                g_z[(size_t)js * NN * HH + row * HH + hh] = z[2 * m + ri];
            }
    }

    // ---- accumulator store ----
    float* accb = g_acc + (size_t)js * NN * CC;
#pragma unroll
    for (int m = 0; m < 2; m++) {
        int row0 = i0 + m0 + 16 * m + gid;
#pragma unroll
        for (int n = 0; n < 8; n++) {
            int col = hh * 64 + n * 8 + tig * 2;
            *(float2*)&accb[(size_t)row0 * CC + col] =
                make_float2(acc[m][n][0], acc[m][n][1]);
            *(float2*)&accb[(size_t)(row0 + 8) * CC + col] =
                make_float2(acc[m][n][2], acc[m][n][3]);
        }
    }
}

// ---------------------------------------------------------------------------
// Kernel 4: finalize, 4 threads per output (h-split x js-split).
// ---------------------------------------------------------------------------
__global__ void k_finalize(float* __restrict__ out) {
    int idx = blockIdx.x * blockDim.x + threadIdx.x;   // 0 .. N*64-1
    int quad = idx & 3;
    int o = idx >> 2;                  // 0 .. N*16-1
    int i = o >> 4, f4 = (o & 15) * 4;
    int jsb   = (quad & 1) * 2;        // js pair: {0,1} or {2,3}
    int hpair = (quad >> 1) * 2;       // heads {0,1} or {2,3}

    float4 A[2];
    float  Z[2];
#pragma unroll
    for (int hq = 0; hq < 2; hq++) {
        int h = hpair + hq;
        A[hq] = make_float4(0.f, 0.f, 0.f, 0.f);
        Z[hq] = 0.f;
#pragma unroll
        for (int jq = 0; jq < 2; jq++) {
            int js = jsb + jq;
            float4 v = *(const float4*)&g_acc[((size_t)js * NN + i) * CC + h * 64 + f4];
            A[hq].x += v.x; A[hq].y += v.y; A[hq].z += v.z; A[hq].w += v.w;
            Z[hq] += g_z[(size_t)js * NN * HH + i * HH + h];
        }
    }
    // combine js halves (lanes differing in bit0)
#pragma unroll
    for (int hq = 0; hq < 2; hq++) {
        A[hq].x += __shfl_xor_sync(0xffffffffu, A[hq].x, 1);
        A[hq].y += __shfl_xor_sync(0xffffffffu, A[hq].y, 1);
        A[hq].z += __shfl_xor_sync(0xffffffffu, A[hq].z, 1);
        A[hq].w += __shfl_xor_sync(0xffffffffu, A[hq].w, 1);
        Z[hq]   += __shfl_xor_sync(0xffffffffu, Z[hq], 1);
    }
    float4 s;
    {
        float r0 = 1.f / Z[0], r1 = 1.f / Z[1];
        s.x = A[0].x * r0 + A[1].x * r1;
        s.y = A[0].y * r0 + A[1].y * r1;
        s.z = A[0].z * r0 + A[1].z * r1;
        s.w = A[0].w * r0 + A[1].w * r1;
    }
    // combine head pairs (lanes differing in bit1)
    s.x += __shfl_xor_sync(0xffffffffu, s.x, 2);
    s.y += __shfl_xor_sync(0xffffffffu, s.y, 2);
    s.z += __shfl_xor_sync(0xffffffffu, s.z, 2);
    s.w += __shfl_xor_sync(0xffffffffu, s.w, 2);
    if (quad == 0)
        *(float4*)&out[i * FF + f4] =
            make_float4(0.25f * s.x, 0.25f * s.y, 0.25f * s.z, 0.25f * s.w);
}

// ---------------------------------------------------------------------------
extern "C" void kernel_launch(void* const* d_in, const int* in_sizes, int n_in,
                              void* d_out, int out_size) {
    const float* x   = (const float*)d_in[0];
    const float* adj = (const float*)d_in[1];
    const float* W   = (const float*)d_in[2];
    const float* a   = (const float*)d_in[3];
    float* out = (float*)d_out;

    cudaFuncSetAttribute(k_attn, cudaFuncAttributeMaxDynamicSharedMemorySize,
                         ATTN_SMEM);

    k_gemm_xw<<<dim3(NN / 64, CC / 64), 256>>>(x, W);
    k_elr<<<NN, 128>>>(a);
    k_attn<<<dim3(NN / ITM, JS), 512, ATTN_SMEM>>>(adj);
    k_finalize<<<(NN * 64) / 512, 512>>>(out);
}

// round 13
// speedup vs baseline: 1.2640x; 1.2640x over previous
#include <cuda_runtime.h>
#include <cuda_fp16.h>
#include <cuda_bf16.h>
#include <cstdint>

// Problem constants
#define NN    4096
#define INF_  256
#define FF    64
#define HH    4
#define CC    256      // HH*FF
#define NEG_SLOPE 0.2f

// Attention tiling
#define JS      4
#define JRANGE  (NN / JS)         // 1024
#define JT      64
#define NTILES  (JRANGE / JT)     // 16
#define ITM     128

// byte-offset smem layout (double buffered)
#define HST_PITCH 144             // bytes/row (72 halfs) -> conflict-free b-frags
#define ADJ_PITCHB 288            // bytes/row (72 floats) -> conflict-free float2
#define HST_BUF  (256 * HST_PITCH)      // 36864 B
#define ADJ_BUF  (ITM * ADJ_PITCHB)     // 36864 B
#define ER_BUF   (HH * JT * 8)          // 2048 B
#define OFF_HST  0
#define OFF_ADJ  (2 * HST_BUF)                 // 73728
#define OFF_ER   (OFF_ADJ + 2 * ADJ_BUF)       // 147456
#define ATTN_SMEM (OFF_ER + 2 * ER_BUF)        // 151552 B

// Scratch (device globals: allocation-free rule)
__device__ float   g_h[NN * CC];           // 4 MB fp32 (for el/er)
__device__ __half  g_hTh[CC * NN];         // 2 MB fp16 transposed [c][node]
__device__ float2  g_eL[NN * HH];          // (exp(el), exp(0.2*el))
__device__ float2  g_eRT[HH * NN];         // transposed [h][node]
__device__ float   g_acc[JS * NN * CC];    // 16 MB partial numerators
__device__ float   g_z[JS * NN * HH];

// ---- packed f32x2 helpers (gemm1) ----
__device__ __forceinline__ unsigned long long pk2(float lo, float hi) {
    unsigned long long r;
    asm("mov.b64 %0, {%1, %2};" : "=l"(r) : "f"(lo), "f"(hi));
    return r;
}
__device__ __forceinline__ void upk2(unsigned long long v, float& lo, float& hi) {
    asm("mov.b64 {%0, %1}, %2;" : "=f"(lo), "=f"(hi) : "l"(v));
}
#define FFMA2(d, a, b) \
    asm("fma.rn.f32x2 %0, %1, %2, %0;" : "+l"(d) : "l"(a), "l"(b))

// pack 2 floats -> half2 reg (hi, lo), round-to-nearest
__device__ __forceinline__ uint32_t h2pk(float hi, float lo) {
    uint32_t d;
    asm("cvt.rn.f16x2.f32 %0, %1, %2;" : "=r"(d) : "f"(hi), "f"(lo));
    return d;
}

// ---- fp16 mma m16n8k16 ----
__device__ __forceinline__ void mma_f16(float* d, uint32_t a0, uint32_t a1,
                                        uint32_t a2, uint32_t a3,
                                        uint32_t b0, uint32_t b1) {
    asm volatile(
        "mma.sync.aligned.m16n8k16.row.col.f32.f16.f16.f32 "
        "{%0,%1,%2,%3}, {%4,%5,%6,%7}, {%8,%9}, {%0,%1,%2,%3};"
        : "+f"(d[0]), "+f"(d[1]), "+f"(d[2]), "+f"(d[3])
        : "r"(a0), "r"(a1), "r"(a2), "r"(a3), "r"(b0), "r"(b1));
}

// ---- cp.async ----
__device__ __forceinline__ uint32_t smem_u32(const void* p) {
    uint32_t a;
    asm("{ .reg .u64 t; cvta.to.shared.u64 t, %1; cvt.u32.u64 %0, t; }"
        : "=r"(a) : "l"(p));
    return a;
}
#define CP16(dst, src) \
    asm volatile("cp.async.cg.shared.global [%0], [%1], 16;" \
                 :: "r"(dst), "l"(src) : "memory")
#define CP_COMMIT() asm volatile("cp.async.commit_group;" ::: "memory")
#define CP_WAIT0()  asm volatile("cp.async.wait_group 0;" ::: "memory")

// ---------------------------------------------------------------------------
// Kernel 1: h = x @ W (fp32). Writes g_h (fp32) and g_hTh (fp16, transposed).
// ---------------------------------------------------------------------------
__global__ void k_gemm_xw(const float* __restrict__ x,
                          const float* __restrict__ W) {
    __shared__ float x_s[64][17];
    __shared__ __align__(16) float W_s[16][64];

    const int t  = threadIdx.x;
    const int i0 = blockIdx.x * 64;
    const int n0 = blockIdx.y * 64;
    const int tcx = t & 15;
    const int trx = t >> 4;

    unsigned long long acc2[4][2];
#pragma unroll
    for (int m = 0; m < 4; m++) { acc2[m][0] = 0ull; acc2[m][1] = 0ull; }

    for (int k0 = 0; k0 < INF_; k0 += 16) {
#pragma unroll
        for (int k = 0; k < 4; k++) {
            int idx = k * 256 + t;
            x_s[idx >> 4][idx & 15] = x[(i0 + (idx >> 4)) * INF_ + k0 + (idx & 15)];
        }
#pragma unroll
        for (int k = 0; k < 4; k++) {
            int idx = k * 256 + t;
            W_s[idx >> 6][idx & 63] = W[(k0 + (idx >> 6)) * CC + n0 + (idx & 63)];
        }
        __syncthreads();
#pragma unroll
        for (int kk = 0; kk < 16; kk++) {
            ulonglong2 B = *(const ulonglong2*)&W_s[kk][tcx * 4];
#pragma unroll
            for (int m = 0; m < 4; m++) {
                float av = x_s[trx * 4 + m][kk];
                unsigned long long a2 = pk2(av, av);
                FFMA2(acc2[m][0], a2, B.x);
                FFMA2(acc2[m][1], a2, B.y);
            }
        }
        __syncthreads();
    }
    float v[4][4];
#pragma unroll
    for (int m = 0; m < 4; m++) {
        upk2(acc2[m][0], v[m][0], v[m][1]);
        upk2(acc2[m][1], v[m][2], v[m][3]);
        *(float4*)&g_h[(size_t)(i0 + trx * 4 + m) * CC + n0 + tcx * 4] =
            make_float4(v[m][0], v[m][1], v[m][2], v[m][3]);
    }
    // transposed fp16 store: g_hTh[c][i], 4 nodes per 8B chunk
#pragma unroll
    for (int cc = 0; cc < 4; cc++) {
        uint2 p;
        p.x = h2pk(v[1][cc], v[0][cc]);
        p.y = h2pk(v[3][cc], v[2][cc]);
        *(uint2*)&g_hTh[(size_t)(n0 + tcx * 4 + cc) * NN + i0 + trx * 4] = p;
    }
}

// ---------------------------------------------------------------------------
// Kernel 2: el/er dots -> factored exponentials (eR stored transposed)
// ---------------------------------------------------------------------------
__global__ void k_elr(const float* __restrict__ a) {
    const int i    = blockIdx.x;
    const int wid  = threadIdx.x >> 5;
    const int lane = threadIdx.x & 31;

    float v1 = g_h[i * CC + wid * FF + lane];
    float v2 = g_h[i * CC + wid * FF + lane + 32];
    float el = v1 * a[lane]      + v2 * a[lane + 32];
    float er = v1 * a[64 + lane] + v2 * a[96 + lane];
#pragma unroll
    for (int off = 16; off > 0; off >>= 1) {
        el += __shfl_xor_sync(0xffffffffu, el, off);
        er += __shfl_xor_sync(0xffffffffu, er, off);
    }
    if (lane == 0) {
        g_eL[i * HH + wid]  = make_float2(__expf(el), __expf(NEG_SLOPE * el));
        g_eRT[wid * NN + i] = make_float2(__expf(er), __expf(NEG_SLOPE * er));
    }
}

// ---------------------------------------------------------------------------
// Kernel 3: fused attention via mma.sync fp16 m16n8k16, cp.async dbl-buffered.
// ---------------------------------------------------------------------------
__global__ void __launch_bounds__(512, 1) k_attn(const float* __restrict__ adj) {
    extern __shared__ __align__(16) char smc[];
    const uint32_t sm_b = smem_u32(smc);

    const int tid  = threadIdx.x;
    const int wid  = tid >> 5;
    const int lane = tid & 31;
    const int hh   = wid >> 2;
    const int wm   = wid & 3;
    const int m0   = wm * 32;
    const int gid  = lane >> 2;    // 0..7
    const int tig  = lane & 3;     // 0..3
    const int i0   = blockIdx.x * ITM;
    const int js   = blockIdx.y;
    const int jbase = js * JRANGE;
    const int cbase = hh * 64 + gid;

    // row exp-factors pinned in registers
    float2 P[4];
#pragma unroll
    for (int m = 0; m < 2; m++)
#pragma unroll
        for (int ri = 0; ri < 2; ri++)
            P[m * 2 + ri] = g_eL[(i0 + m0 + 16 * m + 8 * ri + gid) * HH + hh];

    float acc[2][8][4];
#pragma unroll
    for (int m = 0; m < 2; m++)
#pragma unroll
        for (int n = 0; n < 8; n++)
#pragma unroll
            for (int q = 0; q < 4; q++) acc[m][n][q] = 0.f;
    float z[4] = {0.f, 0.f, 0.f, 0.f};

    // ---- issue staging for tile t into buffer b ----
    auto issue = [&](int t, int b) {
        const int j0 = jbase + t * JT;
        const uint32_t hb = sm_b + OFF_HST + b * HST_BUF;
        const uint32_t ab = sm_b + OFF_ADJ + b * ADJ_BUF;
        const uint32_t eb = sm_b + OFF_ER  + b * ER_BUF;
        // hsT: 256 rows x 64 halves (128B) = 2048 chunks
#pragma unroll
        for (int q = 0; q < 4; q++) {
            int idx = q * 512 + tid;
            int c = idx >> 3, ch = idx & 7;
            CP16(hb + c * HST_PITCH + ch * 16,
                 (const char*)&g_hTh[(size_t)c * NN + j0 + ch * 8]);
        }
        // adj: 128 rows x 64 floats (256B) = 2048 chunks
#pragma unroll
        for (int q = 0; q < 4; q++) {
            int idx = q * 512 + tid;
            int r = idx >> 4, ch = idx & 15;
            CP16(ab + r * ADJ_PITCHB + ch * 16,
                 (const char*)&adj[(size_t)(i0 + r) * NN + j0 + ch * 4]);
        }
        // erT: 4 rows x 64 float2 (512B) = 128 chunks
        if (tid < 128) {
            int h = tid >> 5, ch = tid & 31;
            CP16(eb + h * 512 + ch * 16,
                 (const char*)&g_eRT[(size_t)h * NN + j0] + ch * 16);
        }
        CP_COMMIT();
    };

    issue(0, 0);

    for (int t = 0; t < NTILES; t++) {
        const int b = t & 1;
        CP_WAIT0();
        __syncthreads();               // tile t visible; tile t-1 compute done
        if (t + 1 < NTILES) issue(t + 1, b ^ 1);

        const char* hstb = smc + OFF_HST + b * HST_BUF;
        const char* adjb = smc + OFF_ADJ + b * ADJ_BUF;
        const char* erb  = smc + OFF_ER  + b * ER_BUF;

#pragma unroll
        for (int kk = 0; kk < 4; kk++) {
            const int jb2 = kk * 16 + 2 * tig;     // j offset within tile

            // er pairs: Q[jb2], Q[jb2+1], Q[jb2+8], Q[jb2+9]
            float4 eA = *(const float4*)(erb + hh * 512 + jb2 * 8);
            float4 eB = *(const float4*)(erb + hh * 512 + (jb2 + 8) * 8);

            // B fragments: contiguous half2 loads
            uint32_t b0[8], b1[8];
#pragma unroll
            for (int n = 0; n < 8; n++) {
                const char* hp = hstb + (cbase + n * 8) * HST_PITCH + jb2 * 2;
                b0[n] = *(const uint32_t*)hp;
                b1[n] = *(const uint32_t*)(hp + 16);
            }

#pragma unroll
            for (int m = 0; m < 2; m++) {
                const int ib = m0 + 16 * m + gid;
                const char* ap  = adjb + ib * ADJ_PITCHB + jb2 * 4;
                float2 ad00 = *(const float2*)ap;           // row ib: j, j+1
                float2 ad08 = *(const float2*)(ap + 32);    // row ib: j+8, j+9
                float2 ad80 = *(const float2*)(ap + 8 * ADJ_PITCHB);
                float2 ad88 = *(const float2*)(ap + 8 * ADJ_PITCHB + 32);
                const float2 Pa = P[2 * m], Pb = P[2 * m + 1];

                float w00 = ad00.x * fmaxf(Pa.x * eA.x, Pa.y * eA.y);
                float w01 = ad00.y * fmaxf(Pa.x * eA.z, Pa.y * eA.w);
                float w08 = ad08.x * fmaxf(Pa.x * eB.x, Pa.y * eB.y);
                float w09 = ad08.y * fmaxf(Pa.x * eB.z, Pa.y * eB.w);
                float w80 = ad80.x * fmaxf(Pb.x * eA.x, Pb.y * eA.y);
                float w81 = ad80.y * fmaxf(Pb.x * eA.z, Pb.y * eA.w);
                float w88 = ad88.x * fmaxf(Pb.x * eB.x, Pb.y * eB.y);
                float w89 = ad88.y * fmaxf(Pb.x * eB.z, Pb.y * eB.w);

                z[2 * m]     += (w00 + w01) + (w08 + w09);
                z[2 * m + 1] += (w80 + w81) + (w88 + w89);

                uint32_t a0 = h2pk(w01, w00);
                uint32_t a1 = h2pk(w81, w80);
                uint32_t a2 = h2pk(w09, w08);
                uint32_t a3 = h2pk(w89, w88);
#pragma unroll
                for (int n = 0; n < 8; n++)
                    mma_f16(acc[m][n], a0, a1, a2, a3, b0[n], b1[n]);
            }
        }
    }

    // ---- z reduce across quad lanes ----
#pragma unroll
    for (int q = 0; q < 4; q++) {
        z[q] += __shfl_xor_sync(0xffffffffu, z[q], 1);
        z[q] += __shfl_xor_sync(0xffffffffu, z[q], 2);
    }
    if (tig == 0) {
#pragma unroll
        for (int m = 0; m < 2; m++)
#pragma unroll
            for (int ri = 0; ri < 2; ri++) {
                int row = i0 + m0 + 16 * m + 8 * ri + gid;
                g_z[(size_t)js * NN * HH + row * HH + hh] = z[2 * m + ri];
            }
    }

    // ---- accumulator store ----
    float* accb = g_acc + (size_t)js * NN * CC;
#pragma unroll
    for (int m = 0; m < 2; m++) {
        int row0 = i0 + m0 + 16 * m + gid;
#pragma unroll
        for (int n = 0; n < 8; n++) {
            int col = hh * 64 + n * 8 + tig * 2;
            *(float2*)&accb[(size_t)row0 * CC + col] =
                make_float2(acc[m][n][0], acc[m][n][1]);
            *(float2*)&accb[(size_t)(row0 + 8) * CC + col] =
                make_float2(acc[m][n][2], acc[m][n][3]);
        }
    }
}

// ---------------------------------------------------------------------------
// Kernel 4: finalize, 2 threads per output (h-split), shfl combine.
// ---------------------------------------------------------------------------
__global__ void k_finalize(float* __restrict__ out) {
    int idx = blockIdx.x * blockDim.x + threadIdx.x;   // 0 .. N*32-1
    int half = idx & 1;
    int o = idx >> 1;                  // 0 .. N*16-1
    int i = o >> 4, f4 = (o & 15) * 4;

    float4 s = make_float4(0.f, 0.f, 0.f, 0.f);
#pragma unroll
    for (int hq = 0; hq < 2; hq++) {
        int h = half * 2 + hq;
        float4 A = make_float4(0.f, 0.f, 0.f, 0.f);
        float  Z = 0.f;
#pragma unroll
        for (int js = 0; js < JS; js++) {
            float4 v = *(const float4*)&g_acc[((size_t)js * NN + i) * CC + h * 64 + f4];
            A.x += v.x; A.y += v.y; A.z += v.z; A.w += v.w;
            Z += g_z[(size_t)js * NN * HH + i * HH + h];
        }
        float r = 1.f / Z;
        s.x += A.x * r; s.y += A.y * r; s.z += A.z * r; s.w += A.w * r;
    }
    s.x += __shfl_xor_sync(0xffffffffu, s.x, 1);
    s.y += __shfl_xor_sync(0xffffffffu, s.y, 1);
    s.z += __shfl_xor_sync(0xffffffffu, s.z, 1);
    s.w += __shfl_xor_sync(0xffffffffu, s.w, 1);
    if (half == 0)
        *(float4*)&out[i * FF + f4] =
            make_float4(0.25f * s.x, 0.25f * s.y, 0.25f * s.z, 0.25f * s.w);
}

// ---------------------------------------------------------------------------
extern "C" void kernel_launch(void* const* d_in, const int* in_sizes, int n_in,
                              void* d_out, int out_size) {
    const float* x   = (const float*)d_in[0];
    const float* adj = (const float*)d_in[1];
    const float* W   = (const float*)d_in[2];
    const float* a   = (const float*)d_in[3];
    float* out = (float*)d_out;

    cudaFuncSetAttribute(k_attn, cudaFuncAttributeMaxDynamicSharedMemorySize,
                         ATTN_SMEM);

    k_gemm_xw<<<dim3(NN / 64, CC / 64), 256>>>(x, W);
    k_elr<<<NN, 128>>>(a);
    k_attn<<<dim3(NN / ITM, JS), 512, ATTN_SMEM>>>(adj);
    k_finalize<<<(NN * 32) / 512, 512>>>(out);
}

// round 14
// speedup vs baseline: 1.3343x; 1.0556x over previous
#include <cuda_runtime.h>
#include <cuda_fp16.h>
#include <cuda_bf16.h>
#include <cstdint>

// Problem constants
#define NN    4096
#define INF_  256
#define FF    64
#define HH    4
#define CC    256      // HH*FF
#define NEG_SLOPE 0.2f

// Attention tiling
#define JS      4
#define JRANGE  (NN / JS)         // 1024
#define JT      64
#define NTILES  (JRANGE / JT)     // 16
#define ITM     128

// byte-offset smem layout (double buffered)
#define HST_PITCH 144             // bytes/row (72 halfs) -> conflict-free ldsm
#define ADJ_PITCHB 288            // bytes/row (72 floats) -> conflict-free float2
#define HST_BUF  (256 * HST_PITCH)      // 36864 B
#define ADJ_BUF  (ITM * ADJ_PITCHB)     // 36864 B
#define ER_BUF   (HH * JT * 8)          // 2048 B
#define OFF_HST  0
#define OFF_ADJ  (2 * HST_BUF)                 // 73728
#define OFF_ER   (OFF_ADJ + 2 * ADJ_BUF)       // 147456
#define ATTN_SMEM (OFF_ER + 2 * ER_BUF)        // 151552 B

// Scratch (device globals: allocation-free rule)
__device__ __half  g_hTh[CC * NN];         // 2 MB fp16 transposed [c][node]
__device__ float2  g_eL[NN * HH];          // (exp(el), exp(0.2*el))
__device__ float2  g_eRT[HH * NN];         // transposed [h][node]
__device__ float   g_acc[JS * NN * CC];    // 16 MB partial numerators
__device__ float   g_z[JS * NN * HH];

// ---- packed f32x2 helpers ----
__device__ __forceinline__ unsigned long long pk2(float lo, float hi) {
    unsigned long long r;
    asm("mov.b64 %0, {%1, %2};" : "=l"(r) : "f"(lo), "f"(hi));
    return r;
}
__device__ __forceinline__ void upk2(unsigned long long v, float& lo, float& hi) {
    asm("mov.b64 {%0, %1}, %2;" : "=f"(lo), "=f"(hi) : "l"(v));
}
#define FFMA2(d, a, b) \
    asm("fma.rn.f32x2 %0, %1, %2, %0;" : "+l"(d) : "l"(a), "l"(b))

// packed mul then max of the two halves: max(p.lo*q.lo, p.hi*q.hi)
__device__ __forceinline__ float pmax(unsigned long long p, unsigned long long q) {
    unsigned long long r;
    asm("mul.rn.f32x2 %0, %1, %2;" : "=l"(r) : "l"(p), "l"(q));
    float lo, hi;
    asm("mov.b64 {%0, %1}, %2;" : "=f"(lo), "=f"(hi) : "l"(r));
    return fmaxf(lo, hi);
}

// pack 2 floats -> half2 reg (hi, lo), round-to-nearest
__device__ __forceinline__ uint32_t h2pk(float hi, float lo) {
    uint32_t d;
    asm("cvt.rn.f16x2.f32 %0, %1, %2;" : "=r"(d) : "f"(hi), "f"(lo));
    return d;
}

// ---- fp16 mma m16n8k16 ----
__device__ __forceinline__ void mma_f16(float* d, uint32_t a0, uint32_t a1,
                                        uint32_t a2, uint32_t a3,
                                        uint32_t b0, uint32_t b1) {
    asm volatile(
        "mma.sync.aligned.m16n8k16.row.col.f32.f16.f16.f32 "
        "{%0,%1,%2,%3}, {%4,%5,%6,%7}, {%8,%9}, {%0,%1,%2,%3};"
        : "+f"(d[0]), "+f"(d[1]), "+f"(d[2]), "+f"(d[3])
        : "r"(a0), "r"(a1), "r"(a2), "r"(a3), "r"(b0), "r"(b1));
}

#define LDSM4(r0, r1, r2, r3, addr) \
    asm volatile("ldmatrix.sync.aligned.m8n8.x4.shared.b16 {%0,%1,%2,%3}, [%4];" \
        : "=r"(r0), "=r"(r1), "=r"(r2), "=r"(r3) : "r"(addr))

// ---- cp.async ----
__device__ __forceinline__ uint32_t smem_u32(const void* p) {
    uint32_t a;
    asm("{ .reg .u64 t; cvta.to.shared.u64 t, %1; cvt.u32.u64 %0, t; }"
        : "=r"(a) : "l"(p));
    return a;
}
#define CP16(dst, src) \
    asm volatile("cp.async.cg.shared.global [%0], [%1], 16;" \
                 :: "r"(dst), "l"(src) : "memory")
#define CP_COMMIT() asm volatile("cp.async.commit_group;" ::: "memory")
#define CP_WAIT0()  asm volatile("cp.async.wait_group 0;" ::: "memory")

// ---------------------------------------------------------------------------
// Kernel 1: h = x @ W (fp32 accum). Writes g_hTh (fp16, transposed) and,
// fused in the epilogue, the complete el/er exponential factors for this
// block's head (each block covers one head's 64 features).
// ---------------------------------------------------------------------------
__global__ void k_gemm_xw(const float* __restrict__ x,
                          const float* __restrict__ W,
                          const float* __restrict__ a) {
    __shared__ float x_s[64][17];
    __shared__ __align__(16) float W_s[16][64];

    const int t  = threadIdx.x;
    const int i0 = blockIdx.x * 64;
    const int hy = blockIdx.y;          // head
    const int n0 = hy * 64;
    const int tcx = t & 15;
    const int trx = t >> 4;

    unsigned long long acc2[4][2];
#pragma unroll
    for (int m = 0; m < 4; m++) { acc2[m][0] = 0ull; acc2[m][1] = 0ull; }

    for (int k0 = 0; k0 < INF_; k0 += 16) {
#pragma unroll
        for (int k = 0; k < 4; k++) {
            int idx = k * 256 + t;
            x_s[idx >> 4][idx & 15] = x[(i0 + (idx >> 4)) * INF_ + k0 + (idx & 15)];
        }
#pragma unroll
        for (int k = 0; k < 4; k++) {
            int idx = k * 256 + t;
            W_s[idx >> 6][idx & 63] = W[(k0 + (idx >> 6)) * CC + n0 + (idx & 63)];
        }
        __syncthreads();
#pragma unroll
        for (int kk = 0; kk < 16; kk++) {
            ulonglong2 B = *(const ulonglong2*)&W_s[kk][tcx * 4];
#pragma unroll
            for (int m = 0; m < 4; m++) {
                float av = x_s[trx * 4 + m][kk];
                unsigned long long a2 = pk2(av, av);
                FFMA2(acc2[m][0], a2, B.x);
                FFMA2(acc2[m][1], a2, B.y);
            }
        }
        __syncthreads();
    }
    float v[4][4];
#pragma unroll
    for (int m = 0; m < 4; m++) {
        upk2(acc2[m][0], v[m][0], v[m][1]);
        upk2(acc2[m][1], v[m][2], v[m][3]);
    }
    // transposed fp16 store: g_hTh[c][i], 4 nodes per 8B chunk
#pragma unroll
    for (int cc = 0; cc < 4; cc++) {
        uint2 p;
        p.x = h2pk(v[1][cc], v[0][cc]);
        p.y = h2pk(v[3][cc], v[2][cc]);
        *(uint2*)&g_hTh[(size_t)(n0 + tcx * 4 + cc) * NN + i0 + trx * 4] = p;
    }

    // ---- fused el/er: full dot over this head's 64 features ----
    float pl[4], pr[4];
#pragma unroll
    for (int m = 0; m < 4; m++) {
        pl[m] = 0.f; pr[m] = 0.f;
#pragma unroll
        for (int cc = 0; cc < 4; cc++) {
            int f = tcx * 4 + cc;
            pl[m] += v[m][cc] * a[f];
            pr[m] += v[m][cc] * a[64 + f];
        }
    }
#pragma unroll
    for (int off = 8; off >= 1; off >>= 1) {
#pragma unroll
        for (int m = 0; m < 4; m++) {
            pl[m] += __shfl_xor_sync(0xffffffffu, pl[m], off);
            pr[m] += __shfl_xor_sync(0xffffffffu, pr[m], off);
        }
    }
    if (tcx == 0) {
#pragma unroll
        for (int m = 0; m < 4; m++) {
            int row = i0 + trx * 4 + m;
            g_eL[row * HH + hy]  = make_float2(__expf(pl[m]), __expf(NEG_SLOPE * pl[m]));
            g_eRT[hy * NN + row] = make_float2(__expf(pr[m]), __expf(NEG_SLOPE * pr[m]));
        }
    }
}

// ---------------------------------------------------------------------------
// Kernel 2: fused attention via mma.sync fp16 m16n8k16, cp.async dbl-buffered,
// ldmatrix B fragments, packed-f32x2 w compute.
// ---------------------------------------------------------------------------
__global__ void __launch_bounds__(512, 1) k_attn(const float* __restrict__ adj) {
    extern __shared__ __align__(16) char smc[];
    const uint32_t sm_b = smem_u32(smc);

    const int tid  = threadIdx.x;
    const int wid  = tid >> 5;
    const int lane = tid & 31;
    const int hh   = wid >> 2;
    const int wm   = wid & 3;
    const int m0   = wm * 32;
    const int gid  = lane >> 2;    // 0..7
    const int tig  = lane & 3;     // 0..3
    const int i0   = blockIdx.x * ITM;
    const int js   = blockIdx.y;
    const int jbase = js * JRANGE;

    // ldmatrix row addresses (per-thread): matrix (lane/8), row (lane%8)
    // c = hh*64 + lane  (group covers n-frags 0..3), +32 for n-frags 4..7
    const uint32_t lc0 = (hh * 64 + lane) * HST_PITCH;
    const uint32_t lc1 = lc0 + 32 * HST_PITCH;

    // row exp-factors pinned in registers, pre-packed for mul.f32x2
    unsigned long long P2[4];
#pragma unroll
    for (int m = 0; m < 2; m++)
#pragma unroll
        for (int ri = 0; ri < 2; ri++) {
            float2 p = g_eL[(i0 + m0 + 16 * m + 8 * ri + gid) * HH + hh];
            P2[m * 2 + ri] = pk2(p.x, p.y);
        }

    float acc[2][8][4];
#pragma unroll
    for (int m = 0; m < 2; m++)
#pragma unroll
        for (int n = 0; n < 8; n++)
#pragma unroll
            for (int q = 0; q < 4; q++) acc[m][n][q] = 0.f;
    float z[4] = {0.f, 0.f, 0.f, 0.f};

    // ---- issue staging for tile t into buffer b ----
    auto issue = [&](int t, int b) {
        const int j0 = jbase + t * JT;
        const uint32_t hb = sm_b + OFF_HST + b * HST_BUF;
        const uint32_t ab = sm_b + OFF_ADJ + b * ADJ_BUF;
        const uint32_t eb = sm_b + OFF_ER  + b * ER_BUF;
        // hsT: 256 rows x 64 halves (128B) = 2048 chunks
#pragma unroll
        for (int q = 0; q < 4; q++) {
            int idx = q * 512 + tid;
            int c = idx >> 3, ch = idx & 7;
            CP16(hb + c * HST_PITCH + ch * 16,
                 (const char*)&g_hTh[(size_t)c * NN + j0 + ch * 8]);
        }
        // adj: 128 rows x 64 floats (256B) = 2048 chunks
#pragma unroll
        for (int q = 0; q < 4; q++) {
            int idx = q * 512 + tid;
            int r = idx >> 4, ch = idx & 15;
            CP16(ab + r * ADJ_PITCHB + ch * 16,
                 (const char*)&adj[(size_t)(i0 + r) * NN + j0 + ch * 4]);
        }
        // erT: 4 rows x 64 float2 (512B) = 128 chunks
        if (tid < 128) {
            int h = tid >> 5, ch = tid & 31;
            CP16(eb + h * 512 + ch * 16,
                 (const char*)&g_eRT[(size_t)h * NN + j0] + ch * 16);
        }
        CP_COMMIT();
    };

    issue(0, 0);

    for (int t = 0; t < NTILES; t++) {
        const int b = t & 1;
        CP_WAIT0();
        __syncthreads();               // tile t visible; tile t-1 compute done
        if (t + 1 < NTILES) issue(t + 1, b ^ 1);

        const uint32_t hstA0 = sm_b + OFF_HST + b * HST_BUF + lc0;
        const uint32_t hstA1 = sm_b + OFF_HST + b * HST_BUF + lc1;
        const char* adjb = smc + OFF_ADJ + b * ADJ_BUF;
        const char* erb  = smc + OFF_ER  + b * ER_BUF;

#pragma unroll
        for (int kk = 0; kk < 4; kk++) {
            const int jb2 = kk * 16 + 2 * tig;     // j offset within tile

            // er packed pairs (Qx, Qy) for j, j+1, j+8, j+9
            ulonglong2 eAu = *(const ulonglong2*)(erb + hh * 512 + jb2 * 8);
            ulonglong2 eBu = *(const ulonglong2*)(erb + hh * 512 + (jb2 + 8) * 8);

            // B fragments via ldmatrix.x4 (4 n-frags per instr)
            uint32_t b0[8], b1[8];
            LDSM4(b0[0], b0[1], b0[2], b0[3], hstA0 + kk * 32);
            LDSM4(b0[4], b0[5], b0[6], b0[7], hstA1 + kk * 32);
            LDSM4(b1[0], b1[1], b1[2], b1[3], hstA0 + kk * 32 + 16);
            LDSM4(b1[4], b1[5], b1[6], b1[7], hstA1 + kk * 32 + 16);

#pragma unroll
            for (int m = 0; m < 2; m++) {
                const int ib = m0 + 16 * m + gid;
                const char* ap  = adjb + ib * ADJ_PITCHB + jb2 * 4;
                float2 ad00 = *(const float2*)ap;           // row ib: j, j+1
                float2 ad08 = *(const float2*)(ap + 32);    // row ib: j+8, j+9
                float2 ad80 = *(const float2*)(ap + 8 * ADJ_PITCHB);
                float2 ad88 = *(const float2*)(ap + 8 * ADJ_PITCHB + 32);
                const unsigned long long Pa = P2[2 * m], Pb = P2[2 * m + 1];

                float w00 = ad00.x * pmax(Pa, eAu.x);
                float w01 = ad00.y * pmax(Pa, eAu.y);
                float w08 = ad08.x * pmax(Pa, eBu.x);
                float w09 = ad08.y * pmax(Pa, eBu.y);
                float w80 = ad80.x * pmax(Pb, eAu.x);
                float w81 = ad80.y * pmax(Pb, eAu.y);
                float w88 = ad88.x * pmax(Pb, eBu.x);
                float w89 = ad88.y * pmax(Pb, eBu.y);

                z[2 * m]     += (w00 + w01) + (w08 + w09);
                z[2 * m + 1] += (w80 + w81) + (w88 + w89);

                uint32_t a0 = h2pk(w01, w00);
                uint32_t a1 = h2pk(w81, w80);
                uint32_t a2 = h2pk(w09, w08);
                uint32_t a3 = h2pk(w89, w88);
#pragma unroll
                for (int n = 0; n < 8; n++)
                    mma_f16(acc[m][n], a0, a1, a2, a3, b0[n], b1[n]);
            }
        }
    }

    // ---- z reduce across quad lanes ----
#pragma unroll
    for (int q = 0; q < 4; q++) {
        z[q] += __shfl_xor_sync(0xffffffffu, z[q], 1);
        z[q] += __shfl_xor_sync(0xffffffffu, z[q], 2);
    }
    if (tig == 0) {
#pragma unroll
        for (int m = 0; m < 2; m++)
#pragma unroll
            for (int ri = 0; ri < 2; ri++) {
                int row = i0 + m0 + 16 * m + 8 * ri + gid;
                g_z[(size_t)js * NN * HH + row * HH + hh] = z[2 * m + ri];
            }
    }

    // ---- accumulator store ----
    float* accb = g_acc + (size_t)js * NN * CC;
#pragma unroll
    for (int m = 0; m < 2; m++) {
        int row0 = i0 + m0 + 16 * m + gid;
#pragma unroll
        for (int n = 0; n < 8; n++) {
            int col = hh * 64 + n * 8 + tig * 2;
            *(float2*)&accb[(size_t)row0 * CC + col] =
                make_float2(acc[m][n][0], acc[m][n][1]);
            *(float2*)&accb[(size_t)(row0 + 8) * CC + col] =
                make_float2(acc[m][n][2], acc[m][n][3]);
        }
    }
}

// ---------------------------------------------------------------------------
// Kernel 3: finalize, 2 threads per output (h-split), shfl combine.
// ---------------------------------------------------------------------------
__global__ void k_finalize(float* __restrict__ out) {
    int idx = blockIdx.x * blockDim.x + threadIdx.x;   // 0 .. N*32-1
    int half = idx & 1;
    int o = idx >> 1;                  // 0 .. N*16-1
    int i = o >> 4, f4 = (o & 15) * 4;

    float4 s = make_float4(0.f, 0.f, 0.f, 0.f);
#pragma unroll
    for (int hq = 0; hq < 2; hq++) {
        int h = half * 2 + hq;
        float4 A = make_float4(0.f, 0.f, 0.f, 0.f);
        float  Z = 0.f;
#pragma unroll
        for (int js = 0; js < JS; js++) {
            float4 v = *(const float4*)&g_acc[((size_t)js * NN + i) * CC + h * 64 + f4];
            A.x += v.x; A.y += v.y; A.z += v.z; A.w += v.w;
            Z += g_z[(size_t)js * NN * HH + i * HH + h];
        }
        float r = 1.f / Z;
        s.x += A.x * r; s.y += A.y * r; s.z += A.z * r; s.w += A.w * r;
    }
    s.x += __shfl_xor_sync(0xffffffffu, s.x, 1);
    s.y += __shfl_xor_sync(0xffffffffu, s.y, 1);
    s.z += __shfl_xor_sync(0xffffffffu, s.z, 1);
    s.w += __shfl_xor_sync(0xffffffffu, s.w, 1);
    if (half == 0)
        *(float4*)&out[i * FF + f4] =
            make_float4(0.25f * s.x, 0.25f * s.y, 0.25f * s.z, 0.25f * s.w);
}

// ---------------------------------------------------------------------------
extern "C" void kernel_launch(void* const* d_in, const int* in_sizes, int n_in,
                              void* d_out, int out_size) {
    const float* x   = (const float*)d_in[0];
    const float* adj = (const float*)d_in[1];
    const float* W   = (const float*)d_in[2];
    const float* a   = (const float*)d_in[3];
    float* out = (float*)d_out;

    cudaFuncSetAttribute(k_attn, cudaFuncAttributeMaxDynamicSharedMemorySize,
                         ATTN_SMEM);

    k_gemm_xw<<<dim3(NN / 64, HH), 256>>>(x, W, a);
    k_attn<<<dim3(NN / ITM, JS), 512, ATTN_SMEM>>>(adj);
    k_finalize<<<(NN * 32) / 512, 512>>>(out);
}

// round 17
// speedup vs baseline: 1.4073x; 1.0547x over previous
#include <cuda_runtime.h>
#include <cuda_fp16.h>
#include <cuda_bf16.h>
#include <cstdint>

// Problem constants
#define NN    4096
#define INF_  256
#define FF    64
#define HH    4
#define CC    256      // HH*FF
#define NEG_SLOPE 0.2f

// Attention tiling
#define JS      4
#define JRANGE  (NN / JS)         // 1024
#define JT      64
#define NTILES  (JRANGE / JT)     // 16
#define ITM     128

// k_attn smem layout (double buffered)
#define HST_PITCH 144             // bytes/row (72 halfs) -> conflict-free ldsm
#define ADJ_PITCHB 288            // bytes/row -> conflict-free float2
#define HST_BUF  (256 * HST_PITCH)      // 36864 B
#define ADJ_BUF  (ITM * ADJ_PITCHB)     // 36864 B
#define ER_BUF   (HH * JT * 8)          // 2048 B
#define OFF_HST  0
#define OFF_ADJ  (2 * HST_BUF)
#define OFF_ER   (OFF_ADJ + 2 * ADJ_BUF)
#define ATTN_SMEM (OFF_ER + 2 * ER_BUF)        // 151552 B

// k_gemm_h smem: x tile 128x528B + w tile 64x528B
#define GH_PITCH 528
#define GH_SMEM  (128 * GH_PITCH + 64 * GH_PITCH)   // 101376 B

// Scratch (device globals: allocation-free rule)
__device__ __half  g_xh[NN * INF_];        // 2 MB fp16 x
__device__ __half  g_WTh[CC * INF_];       // 128 KB fp16 W transposed [c][k]
__device__ float2  g_u[INF_ * HH];         // (u_l, u_r) per (k, h)
__device__ __half  g_hTh[CC * NN];         // 2 MB fp16 h transposed [c][node]
__device__ float2  g_eL[NN * HH];          // (exp(el), exp(0.2*el))
__device__ float2  g_eRT[HH * NN];         // transposed [h][node]
__device__ float   g_acc[JS * NN * CC];    // 16 MB partial numerators
__device__ float   g_z[JS * NN * HH];

// ---- helpers ----
__device__ __forceinline__ unsigned long long pk2(float lo, float hi) {
    unsigned long long r;
    asm("mov.b64 %0, {%1, %2};" : "=l"(r) : "f"(lo), "f"(hi));
    return r;
}
// packed mul then max of the two halves: max(p.lo*q.lo, p.hi*q.hi)
__device__ __forceinline__ float pmax(unsigned long long p, unsigned long long q) {
    unsigned long long r;
    asm("mul.rn.f32x2 %0, %1, %2;" : "=l"(r) : "l"(p), "l"(q));
    float lo, hi;
    asm("mov.b64 {%0, %1}, %2;" : "=f"(lo), "=f"(hi) : "l"(r));
    return fmaxf(lo, hi);
}
// pack 2 floats -> half2 reg (hi, lo), round-to-nearest
__device__ __forceinline__ uint32_t h2pk(float hi, float lo) {
    uint32_t d;
    asm("cvt.rn.f16x2.f32 %0, %1, %2;" : "=r"(d) : "f"(hi), "f"(lo));
    return d;
}
__device__ __forceinline__ void mma_f16(float* d, uint32_t a0, uint32_t a1,
                                        uint32_t a2, uint32_t a3,
                                        uint32_t b0, uint32_t b1) {
    asm volatile(
        "mma.sync.aligned.m16n8k16.row.col.f32.f16.f16.f32 "
        "{%0,%1,%2,%3}, {%4,%5,%6,%7}, {%8,%9}, {%0,%1,%2,%3};"
        : "+f"(d[0]), "+f"(d[1]), "+f"(d[2]), "+f"(d[3])
        : "r"(a0), "r"(a1), "r"(a2), "r"(a3), "r"(b0), "r"(b1));
}
#define LDSM4(r0, r1, r2, r3, addr) \
    asm volatile("ldmatrix.sync.aligned.m8n8.x4.shared.b16 {%0,%1,%2,%3}, [%4];" \
        : "=r"(r0), "=r"(r1), "=r"(r2), "=r"(r3) : "r"(addr))
__device__ __forceinline__ uint32_t smem_u32(const void* p) {
    uint32_t a;
    asm("{ .reg .u64 t; cvta.to.shared.u64 t, %1; cvt.u32.u64 %0, t; }"
        : "=r"(a) : "l"(p));
    return a;
}
#define CP16(dst, src) \
    asm volatile("cp.async.cg.shared.global [%0], [%1], 16;" \
                 :: "r"(dst), "l"(src) : "memory")
#define CP_COMMIT() asm volatile("cp.async.commit_group;" ::: "memory")
#define CP_WAIT0()  asm volatile("cp.async.wait_group 0;" ::: "memory")

// ---------------------------------------------------------------------------
// Kernel 0: prep. W -> g_WTh (fp16, [c][k]) and u[k][h] = (W[k,:]·a_l, ·a_r).
// Grid 16 blocks x 256 threads; block covers 16 k-rows.
// ---------------------------------------------------------------------------
__global__ void k_prep(const float* __restrict__ W, const float* __restrict__ a) {
    __shared__ float Ws[16][260];
    const int tid = threadIdx.x;
    const int k0  = blockIdx.x * 16;

#pragma unroll
    for (int q = 0; q < 4; q++) {
        int idx = q * 256 + tid;
        int r = idx >> 6, c4 = (idx & 63) * 4;
        *(float4*)&Ws[r][c4] = *(const float4*)&W[(k0 + r) * CC + c4];
    }
    __syncthreads();

    // transposed fp16 write: thread = output row c = tid
    {
        uint32_t p[8];
#pragma unroll
        for (int j = 0; j < 8; j++)
            p[j] = h2pk(Ws[2 * j + 1][tid], Ws[2 * j][tid]);
        uint4 v0 = make_uint4(p[0], p[1], p[2], p[3]);
        uint4 v1 = make_uint4(p[4], p[5], p[6], p[7]);
        *(uint4*)&g_WTh[tid * INF_ + k0]     = v0;
        *(uint4*)&g_WTh[tid * INF_ + k0 + 8] = v1;
    }

    // u: tid = (k<<4) | (h<<2) | (lr<<1) | fh
    {
        const int k  = tid >> 4;
        const int h  = (tid >> 2) & 3;
        const int lr = (tid >> 1) & 1;
        const int fh = tid & 1;
        const int rot = (tid & 15) * 2;
        float p = 0.f;
#pragma unroll
        for (int f = 0; f < 32; f++) {
            int ff = (f + rot) & 31;
            p += Ws[k][h * 64 + fh * 32 + ff] * a[lr * 64 + fh * 32 + ff];
        }
        p += __shfl_xor_sync(0xffffffffu, p, 1);          // combine f-halves
        float other = __shfl_xor_sync(0xffffffffu, p, 2); // partner lr
        if ((tid & 3) == 0)
            g_u[(k0 + k) * HH + h] = make_float2(p, other);
    }
}

// ---------------------------------------------------------------------------
// Kernel 1: per-node el/er (fp32, via u) + x -> fp16 conversion.
// Grid 512 x 256 thr; warp per node.
// ---------------------------------------------------------------------------
__global__ void k_el(const float* __restrict__ x) {
    const int wid  = threadIdx.x >> 5;
    const int lane = threadIdx.x & 31;
    const int n = blockIdx.x * 8 + wid;

    float4 xv0 = *(const float4*)&x[(size_t)n * INF_ + lane * 4];
    float4 xv1 = *(const float4*)&x[(size_t)n * INF_ + 128 + lane * 4];

    // fp16 store
    uint2 s0 = make_uint2(h2pk(xv0.y, xv0.x), h2pk(xv0.w, xv0.z));
    uint2 s1 = make_uint2(h2pk(xv1.y, xv1.x), h2pk(xv1.w, xv1.z));
    *(uint2*)&g_xh[(size_t)n * INF_ + lane * 4]       = s0;
    *(uint2*)&g_xh[(size_t)n * INF_ + 128 + lane * 4] = s1;

    float pl[4] = {0.f, 0.f, 0.f, 0.f};
    float pr[4] = {0.f, 0.f, 0.f, 0.f};
#pragma unroll
    for (int q = 0; q < 2; q++) {
        float xa[4];
        if (q == 0) { xa[0]=xv0.x; xa[1]=xv0.y; xa[2]=xv0.z; xa[3]=xv0.w; }
        else        { xa[0]=xv1.x; xa[1]=xv1.y; xa[2]=xv1.z; xa[3]=xv1.w; }
        const int cb = q * 128 + lane * 4;
#pragma unroll
        for (int cc = 0; cc < 4; cc++) {
            const float4 u01 = __ldg((const float4*)&g_u[(cb + cc) * HH + 0]);
            const float4 u23 = __ldg((const float4*)&g_u[(cb + cc) * HH + 2]);
            pl[0] += xa[cc] * u01.x;  pr[0] += xa[cc] * u01.y;
            pl[1] += xa[cc] * u01.z;  pr[1] += xa[cc] * u01.w;
            pl[2] += xa[cc] * u23.x;  pr[2] += xa[cc] * u23.y;
            pl[3] += xa[cc] * u23.z;  pr[3] += xa[cc] * u23.w;
        }
    }
#pragma unroll
    for (int off = 16; off >= 1; off >>= 1) {
#pragma unroll
        for (int h = 0; h < 4; h++) {
            pl[h] += __shfl_xor_sync(0xffffffffu, pl[h], off);
            pr[h] += __shfl_xor_sync(0xffffffffu, pr[h], off);
        }
    }
    if (lane == 0) {
#pragma unroll
        for (int h = 0; h < 4; h++) {
            g_eL[n * HH + h]  = make_float2(__expf(pl[h]), __expf(NEG_SLOPE * pl[h]));
            g_eRT[h * NN + n] = make_float2(__expf(pr[h]), __expf(NEG_SLOPE * pr[h]));
        }
    }
}

// ---------------------------------------------------------------------------
// Kernel 2: h = x @ W via fp16 mma (fp32 accum), output g_hTh fp16 [c][node].
// Grid (32, 4): block tile M=128 (nodes) x N=64 (features), K=256. 256 thr.
// ---------------------------------------------------------------------------
__global__ void __launch_bounds__(256, 1) k_gemm_h() {
    extern __shared__ __align__(16) char gsm[];
    const uint32_t sb = smem_u32(gsm);
    const uint32_t xs = sb;
    const uint32_t ws = sb + 128 * GH_PITCH;

    const int tid  = threadIdx.x;
    const int wid  = tid >> 5;
    const int lane = tid & 31;
    const int wr = wid & 3;       // m-group: rows wr*32
    const int wc = wid >> 2;      // n-group: cols wc*32
    const int i0 = blockIdx.x * 128;
    const int n0 = blockIdx.y * 64;

    // stage x tile: 128 rows x 512B
#pragma unroll
    for (int q = 0; q < 16; q++) {
        int idx = q * 256 + tid;
        int r = idx >> 5, ch = idx & 31;
        CP16(xs + r * GH_PITCH + ch * 16,
             (const char*)g_xh + (size_t)(i0 + r) * 512 + ch * 16);
    }
    // stage w tile: 64 rows x 512B
#pragma unroll
    for (int q = 0; q < 8; q++) {
        int idx = q * 256 + tid;
        int r = idx >> 5, ch = idx & 31;
        CP16(ws + r * GH_PITCH + ch * 16,
             (const char*)g_WTh + (size_t)(n0 + r) * 512 + ch * 16);
    }
    CP_COMMIT();
    CP_WAIT0();
    __syncthreads();

    // ldmatrix addresses
    const int sel = lane >> 3, l8 = lane & 7;
    const uint32_t aA = xs + (wr * 32 + (sel & 1) * 8 + l8) * GH_PITCH + (sel >> 1) * 16;
    const uint32_t aB = ws + (wc * 32 + (sel >> 1) * 8 + l8) * GH_PITCH + (sel & 1) * 16;

    float acc[2][4][4];
#pragma unroll
    for (int m = 0; m < 2; m++)
#pragma unroll
        for (int nf = 0; nf < 4; nf++)
#pragma unroll
            for (int q = 0; q < 4; q++) acc[m][nf][q] = 0.f;

#pragma unroll
    for (int ks = 0; ks < 16; ks++) {
        uint32_t a0[4], a1[4], b0[4], b1[4];
        LDSM4(a0[0], a0[1], a0[2], a0[3], aA + ks * 32);
        LDSM4(a1[0], a1[1], a1[2], a1[3], aA + 16 * GH_PITCH + ks * 32);
        LDSM4(b0[0], b0[1], b0[2], b0[3], aB + ks * 32);
        LDSM4(b1[0], b1[1], b1[2], b1[3], aB + 16 * GH_PITCH + ks * 32);
#pragma unroll
        for (int m = 0; m < 2; m++) {
            uint32_t* am = m ? a1 : a0;
            mma_f16(acc[m][0], am[0], am[1], am[2], am[3], b0[0], b0[1]);
            mma_f16(acc[m][1], am[0], am[1], am[2], am[3], b0[2], b0[3]);
            mma_f16(acc[m][2], am[0], am[1], am[2], am[3], b1[0], b1[1]);
            mma_f16(acc[m][3], am[0], am[1], am[2], am[3], b1[2], b1[3]);
        }
    }
    __syncthreads();

    // transpose epilogue through smem: os[64 cols][136 halfs pitch]
    __half* os = (__half*)gsm;
#pragma unroll
    for (int m = 0; m < 2; m++)
#pragma unroll
        for (int nf = 0; nf < 4; nf++)
#pragma unroll
            for (int q = 0; q < 4; q++) {
                int col = wc * 32 + nf * 8 + (lane & 3) * 2 + (q & 1);
                int row = wr * 32 + m * 16 + (lane >> 2) + (q >> 1) * 8;
                os[col * 136 + row] = __float2half_rn(acc[m][nf][q]);
            }
    __syncthreads();
#pragma unroll
    for (int q = 0; q < 4; q++) {
        int idx = q * 256 + tid;
        int col = idx >> 4, ch = idx & 15;
        *(uint4*)&g_hTh[(size_t)(n0 + col) * NN + i0 + ch * 8] =
            *(const uint4*)&os[col * 136 + ch * 8];
    }
}

// ---------------------------------------------------------------------------
// Kernel 3: fused attention via mma.sync fp16 m16n8k16, cp.async dbl-buffered.
// ---------------------------------------------------------------------------
__global__ void __launch_bounds__(512, 1) k_attn(const float* __restrict__ adj) {
    extern __shared__ __align__(16) char smc[];
    const uint32_t sm_b = smem_u32(smc);

    const int tid  = threadIdx.x;
    const int wid  = tid >> 5;
    const int lane = tid & 31;
    const int hh   = wid >> 2;
    const int wm   = wid & 3;
    const int m0   = wm * 32;
    const int gid  = lane >> 2;
    const int tig  = lane & 3;
    const int i0   = blockIdx.x * ITM;
    const int js   = blockIdx.y;
    const int jbase = js * JRANGE;

    const uint32_t lc0 = (hh * 64 + lane) * HST_PITCH;
    const uint32_t lc1 = lc0 + 32 * HST_PITCH;

    unsigned long long P2[4];
#pragma unroll
    for (int m = 0; m < 2; m++)
#pragma unroll
        for (int ri = 0; ri < 2; ri++) {
            float2 p = g_eL[(i0 + m0 + 16 * m + 8 * ri + gid) * HH + hh];
            P2[m * 2 + ri] = pk2(p.x, p.y);
        }

    float acc[2][8][4];
#pragma unroll
    for (int m = 0; m < 2; m++)
#pragma unroll
        for (int n = 0; n < 8; n++)
#pragma unroll
            for (int q = 0; q < 4; q++) acc[m][n][q] = 0.f;
    float z[4] = {0.f, 0.f, 0.f, 0.f};

    auto issue = [&](int t, int b) {
        const int j0 = jbase + t * JT;
        const uint32_t hb = sm_b + OFF_HST + b * HST_BUF;
        const uint32_t ab = sm_b + OFF_ADJ + b * ADJ_BUF;
        const uint32_t eb = sm_b + OFF_ER  + b * ER_BUF;
#pragma unroll
        for (int q = 0; q < 4; q++) {
            int idx = q * 512 + tid;
            int c = idx >> 3, ch = idx & 7;
            CP16(hb + c * HST_PITCH + ch * 16,
                 (const char*)&g_hTh[(size_t)c * NN + j0 + ch * 8]);
        }
#pragma unroll
        for (int q = 0; q < 4; q++) {
            int idx = q * 512 + tid;
            int r = idx >> 4, ch = idx & 15;
            CP16(ab + r * ADJ_PITCHB + ch * 16,
                 (const char*)&adj[(size_t)(i0 + r) * NN + j0 + ch * 4]);
        }
        if (tid < 128) {
            int h = tid >> 5, ch = tid & 31;
            CP16(eb + h * 512 + ch * 16,
                 (const char*)&g_eRT[(size_t)h * NN + j0] + ch * 16);
        }
        CP_COMMIT();
    };

    issue(0, 0);

    for (int t = 0; t < NTILES; t++) {
        const int b = t & 1;
        CP_WAIT0();
        __syncthreads();
        if (t + 1 < NTILES) issue(t + 1, b ^ 1);

        const uint32_t hstA0 = sm_b + OFF_HST + b * HST_BUF + lc0;
        const uint32_t hstA1 = sm_b + OFF_HST + b * HST_BUF + lc1;
        const char* adjb = smc + OFF_ADJ + b * ADJ_BUF;
        const char* erb  = smc + OFF_ER  + b * ER_BUF;

#pragma unroll
        for (int kk = 0; kk < 4; kk++) {
            const int jb2 = kk * 16 + 2 * tig;

            ulonglong2 eAu = *(const ulonglong2*)(erb + hh * 512 + jb2 * 8);
            ulonglong2 eBu = *(const ulonglong2*)(erb + hh * 512 + (jb2 + 8) * 8);

            uint32_t b0[8], b1[8];
            LDSM4(b0[0], b0[1], b0[2], b0[3], hstA0 + kk * 32);
            LDSM4(b0[4], b0[5], b0[6], b0[7], hstA1 + kk * 32);
            LDSM4(b1[0], b1[1], b1[2], b1[3], hstA0 + kk * 32 + 16);
            LDSM4(b1[4], b1[5], b1[6], b1[7], hstA1 + kk * 32 + 16);

#pragma unroll
            for (int m = 0; m < 2; m++) {
                const int ib = m0 + 16 * m + gid;
                const char* ap  = adjb + ib * ADJ_PITCHB + jb2 * 4;
                float2 ad00 = *(const float2*)ap;
                float2 ad08 = *(const float2*)(ap + 32);
                float2 ad80 = *(const float2*)(ap + 8 * ADJ_PITCHB);
                float2 ad88 = *(const float2*)(ap + 8 * ADJ_PITCHB + 32);
                const unsigned long long Pa = P2[2 * m], Pb = P2[2 * m + 1];

                float w00 = ad00.x * pmax(Pa, eAu.x);
                float w01 = ad00.y * pmax(Pa, eAu.y);
                float w08 = ad08.x * pmax(Pa, eBu.x);
                float w09 = ad08.y * pmax(Pa, eBu.y);
                float w80 = ad80.x * pmax(Pb, eAu.x);
                float w81 = ad80.y * pmax(Pb, eAu.y);
                float w88 = ad88.x * pmax(Pb, eBu.x);
                float w89 = ad88.y * pmax(Pb, eBu.y);

                z[2 * m]     += (w00 + w01) + (w08 + w09);
                z[2 * m + 1] += (w80 + w81) + (w88 + w89);

                uint32_t a0 = h2pk(w01, w00);
                uint32_t a1 = h2pk(w81, w80);
                uint32_t a2 = h2pk(w09, w08);
                uint32_t a3 = h2pk(w89, w88);
#pragma unroll
                for (int n = 0; n < 8; n++)
                    mma_f16(acc[m][n], a0, a1, a2, a3, b0[n], b1[n]);
            }
        }
    }

#pragma unroll
    for (int q = 0; q < 4; q++) {
        z[q] += __shfl_xor_sync(0xffffffffu, z[q], 1);
        z[q] += __shfl_xor_sync(0xffffffffu, z[q], 2);
    }
    if (tig == 0) {
#pragma unroll
        for (int m = 0; m < 2; m++)
#pragma unroll
            for (int ri = 0; ri < 2; ri++) {
                int row = i0 + m0 + 16 * m + 8 * ri + gid;
                g_z[(size_t)js * NN * HH + row * HH + hh] = z[2 * m + ri];
            }
    }

    float* accb = g_acc + (size_t)js * NN * CC;
#pragma unroll
    for (int m = 0; m < 2; m++) {
        int row0 = i0 + m0 + 16 * m + gid;
#pragma unroll
        for (int n = 0; n < 8; n++) {
            int col = hh * 64 + n * 8 + tig * 2;
            *(float2*)&accb[(size_t)row0 * CC + col] =
                make_float2(acc[m][n][0], acc[m][n][1]);
            *(float2*)&accb[(size_t)(row0 + 8) * CC + col] =
                make_float2(acc[m][n][2], acc[m][n][3]);
        }
    }
}

// ---------------------------------------------------------------------------
// Kernel 4: finalize, 2 threads per output (h-split), shfl combine.
// ---------------------------------------------------------------------------
__global__ void k_finalize(float* __restrict__ out) {
    int idx = blockIdx.x * blockDim.x + threadIdx.x;
    int half = idx & 1;
    int o = idx >> 1;
    int i = o >> 4, f4 = (o & 15) * 4;

    float4 s = make_float4(0.f, 0.f, 0.f, 0.f);
#pragma unroll
    for (int hq = 0; hq < 2; hq++) {
        int h = half * 2 + hq;
        float4 A = make_float4(0.f, 0.f, 0.f, 0.f);
        float  Z = 0.f;
#pragma unroll
        for (int js = 0; js < JS; js++) {
            float4 v = *(const float4*)&g_acc[((size_t)js * NN + i) * CC + h * 64 + f4];
            A.x += v.x; A.y += v.y; A.z += v.z; A.w += v.w;
            Z += g_z[(size_t)js * NN * HH + i * HH + h];
        }
        float r = 1.f / Z;
        s.x += A.x * r; s.y += A.y * r; s.z += A.z * r; s.w += A.w * r;
    }
    s.x += __shfl_xor_sync(0xffffffffu, s.x, 1);
    s.y += __shfl_xor_sync(0xffffffffu, s.y, 1);
    s.z += __shfl_xor_sync(0xffffffffu, s.z, 1);
    s.w += __shfl_xor_sync(0xffffffffu, s.w, 1);
    if (half == 0)
        *(float4*)&out[i * FF + f4] =
            make_float4(0.25f * s.x, 0.25f * s.y, 0.25f * s.z, 0.25f * s.w);
}

// ---------------------------------------------------------------------------
extern "C" void kernel_launch(void* const* d_in, const int* in_sizes, int n_in,
                              void* d_out, int out_size) {
    const float* x   = (const float*)d_in[0];
    const float* adj = (const float*)d_in[1];
    const float* W   = (const float*)d_in[2];
    const float* a   = (const float*)d_in[3];
    float* out = (float*)d_out;

    cudaFuncSetAttribute(k_attn, cudaFuncAttributeMaxDynamicSharedMemorySize,
                         ATTN_SMEM);
    cudaFuncSetAttribute(k_gemm_h, cudaFuncAttributeMaxDynamicSharedMemorySize,
                         GH_SMEM);

    k_prep<<<16, 256>>>(W, a);
    k_el<<<NN / 8, 256>>>(x);
    k_gemm_h<<<dim3(NN / 128, CC / 64), 256, GH_SMEM>>>();
    k_attn<<<dim3(NN / ITM, JS), 512, ATTN_SMEM>>>(adj);
    k_finalize<<<(NN * 32) / 512, 512>>>(out);
}